// round 3
// baseline (speedup 1.0000x reference)
#include <cuda_runtime.h>

// Problem constants (fixed by setup_inputs): b=2, s=4096, h=16, p=n=64, BL=64
#define NB   2
#define NH   16
#define NC   64
#define BL   64
#define PAD  68    // smem row stride (floats), multiple of 4 for float4 rows

// Scratch (allocation-free rule: __device__ globals)
__device__ float g_states[NB*NH*NC*64*64];   // per-chunk states, layout [n][p]
__device__ float g_S[NB*NH*NC*64*64];        // scanned states, layout [n][p]
__device__ float g_ecl[NB*NH*NC*BL];         // exp(cumsum) per position
__device__ float g_tot[NB*NH*NC];            // chunk total of A

// ---------------------------------------------------------------------------
// Pass 1: one 64x64 tile per 64-thread CTA, 8x8 micro-tile per thread.
// Smem tiles (k-major operands):
//   Xs : X[s][p] row-major (k-major for GEMM2/3, k=s/l)
//   T1 : Ct[n][l]  -> after GEMM1 becomes Gt[s][l] (k-major for GEMM2)
//   T2 : Bt[n][s]  -> after GEMM1 reloaded as B[l][n] row-major (GEMM3)
// ---------------------------------------------------------------------------
__global__ void __launch_bounds__(64) pass1_kernel(
    const float* __restrict__ X, const float* __restrict__ A,
    const float* __restrict__ B, const float* __restrict__ C,
    float* __restrict__ Y)
{
    extern __shared__ float sm[];
    float* Xs = sm;
    float* T1 = sm + 64*PAD;
    float* T2 = sm + 2*64*PAD;
    __shared__ float s_cs[64], s_ecl[64], s_em[64], s_w[64];

    const int c = blockIdx.x, h = blockIdx.y, b = blockIdx.z;
    const int bhc = (b*NH + h)*NC + c;
    const int tid = threadIdx.x;
    const int tx = tid & 7, ty = tid >> 3;
    const size_t base = ((size_t)((b*4096 + c*BL)*NH + h))*64;

    const float aval = A[(size_t)(b*4096 + c*BL + tid)*NH + h];

    // ---- cooperative tile loads: Xs straight; C,B transposed (rotated STS) ----
    #pragma unroll
    for (int i = 0; i < 8; i++) {
        const int row = i*8 + ty;
        const size_t g = base + (size_t)row*1024 + tx*8;
        float4 x0 = *(const float4*)(X + g);
        float4 x1 = *(const float4*)(X + g + 4);
        *(float4*)(Xs + row*PAD + tx*8)     = x0;
        *(float4*)(Xs + row*PAD + tx*8 + 4) = x1;
        float4 c0 = *(const float4*)(C + g);
        float4 c1 = *(const float4*)(C + g + 4);
        float4 b0 = *(const float4*)(B + g);
        float4 b1 = *(const float4*)(B + g + 4);
        const float* cp0 = (const float*)&c0; const float* cp1 = (const float*)&c1;
        const float* bp0 = (const float*)&b0; const float* bp1 = (const float*)&b1;
        #pragma unroll
        for (int q = 0; q < 4; q++) {
            const int e = (q + tx + ty) & 3;                // rotation: 2-way max
            T1[(tx*8 + e)*PAD + row]     = cp0[e];
            T1[(tx*8 + 4 + e)*PAD + row] = cp1[e];
            T2[(tx*8 + e)*PAD + row]     = bp0[e];
            T2[(tx*8 + 4 + e)*PAD + row] = bp1[e];
        }
    }

    // ---- inclusive cumsum of A over 64 positions (2 warps) ----
    {
        float v = aval;
        #pragma unroll
        for (int o = 1; o < 32; o <<= 1) {
            float t = __shfl_up_sync(0xffffffffu, v, o);
            if ((tid & 31) >= o) v += t;
        }
        s_cs[tid] = v;
    }
    __syncthreads();
    if (tid >= 32) s_cs[tid] += s_cs[31];
    __syncthreads();
    {
        const float csl   = s_cs[tid];
        const float total = s_cs[63];
        const float ecl   = expf(csl);
        s_ecl[tid] = ecl;                     // exp(cs[l])
        s_em[tid]  = expf(aval - csl);        // exp(A[s]-cs[s])
        s_w[tid]   = expf(total - csl);       // decay_states
        g_ecl[bhc*64 + tid] = ecl;
        if (tid == 63) g_tot[bhc] = csl;
    }
    __syncthreads();

    const int rb = ty*8, cb = tx*8;

    // ---- GEMM 1: Gt[s][l] = sum_n Bt[n][s] * Ct[n][l] ----
    float acc[8][8] = {};
    #pragma unroll 4
    for (int k = 0; k < 64; k++) {
        float a[8], bb[8];
        *(float4*)(a)      = *(const float4*)(T2 + k*PAD + rb);
        *(float4*)(a + 4)  = *(const float4*)(T2 + k*PAD + rb + 4);
        *(float4*)(bb)     = *(const float4*)(T1 + k*PAD + cb);
        *(float4*)(bb + 4) = *(const float4*)(T1 + k*PAD + cb + 4);
        #pragma unroll
        for (int i = 0; i < 8; i++)
            #pragma unroll
            for (int j = 0; j < 8; j++)
                acc[i][j] += a[i] * bb[j];
    }
    __syncthreads();   // GEMM1 reads of T1/T2 complete

    // masked Gt store over T1: Gt[s][l] = (l>=s) ? G*exp(cs[l])*exp(A[s]-cs[s]) : 0
    #pragma unroll
    for (int i = 0; i < 8; i++) {
        const int s = rb + i;
        const float em = s_em[s];
        float o[8];
        #pragma unroll
        for (int j = 0; j < 8; j++) {
            const int l = cb + j;
            o[j] = (l >= s) ? acc[i][j] * s_ecl[l] * em : 0.f;
        }
        *(float4*)(T1 + s*PAD + cb)     = make_float4(o[0], o[1], o[2], o[3]);
        *(float4*)(T1 + s*PAD + cb + 4) = make_float4(o[4], o[5], o[6], o[7]);
    }
    // reload B row-major into T2 (L2-hot) for GEMM3
    #pragma unroll
    for (int i = 0; i < 8; i++) {
        const int row = i*8 + ty;
        const size_t g = base + (size_t)row*1024 + tx*8;
        *(float4*)(T2 + row*PAD + tx*8)     = *(const float4*)(B + g);
        *(float4*)(T2 + row*PAD + tx*8 + 4) = *(const float4*)(B + g + 4);
    }
    __syncthreads();

    // ---- fused GEMM 2+3 over shared k and shared Xs operand ----
    // GEMM2: Y[l][p]   = sum_s Gt[s][l] * X[s][p]
    // GEMM3: St[n][p]  = sum_l (B[l][n]*w[l]) * X[l][p]
    float yacc[8][8] = {};
    float sacc[8][8] = {};
    #pragma unroll 2
    for (int k = 0; k < 64; k++) {
        float bx[8], g1[8], b2[8];
        *(float4*)(bx)     = *(const float4*)(Xs + k*PAD + cb);
        *(float4*)(bx + 4) = *(const float4*)(Xs + k*PAD + cb + 4);
        *(float4*)(g1)     = *(const float4*)(T1 + k*PAD + rb);
        *(float4*)(g1 + 4) = *(const float4*)(T1 + k*PAD + rb + 4);
        *(float4*)(b2)     = *(const float4*)(T2 + k*PAD + rb);
        *(float4*)(b2 + 4) = *(const float4*)(T2 + k*PAD + rb + 4);
        const float wl = s_w[k];
        #pragma unroll
        for (int i = 0; i < 8; i++) b2[i] *= wl;
        #pragma unroll
        for (int i = 0; i < 8; i++)
            #pragma unroll
            for (int j = 0; j < 8; j++) {
                yacc[i][j] += g1[i] * bx[j];
                sacc[i][j] += b2[i] * bx[j];
            }
    }

    // stores: Y_diag direct; St to g_states [n][p]
    #pragma unroll
    for (int i = 0; i < 8; i++) {
        float* yp = Y + base + (size_t)(rb + i)*1024 + cb;
        *(float4*)(yp)     = make_float4(yacc[i][0], yacc[i][1], yacc[i][2], yacc[i][3]);
        *(float4*)(yp + 4) = make_float4(yacc[i][4], yacc[i][5], yacc[i][6], yacc[i][7]);
    }
    float* st = g_states + (size_t)bhc*4096;
    #pragma unroll
    for (int i = 0; i < 8; i++) {
        *(float4*)(st + (rb+i)*64 + cb)     = make_float4(sacc[i][0], sacc[i][1], sacc[i][2], sacc[i][3]);
        *(float4*)(st + (rb+i)*64 + cb + 4) = make_float4(sacc[i][4], sacc[i][5], sacc[i][6], sacc[i][7]);
    }
}

// ---------------------------------------------------------------------------
// Pass 2: inter-chunk scan per (b,h). S_{c+1} = exp(tot_c)*(S_c + state_c).
// ---------------------------------------------------------------------------
__global__ void __launch_bounds__(256) pass2_kernel()
{
    const int bh  = blockIdx.x;
    const int tid = threadIdx.x;
    const float4* st = (const float4*)(g_states + (size_t)bh*NC*4096);
    float4*       so = (float4*)(g_S + (size_t)bh*NC*4096);
    float4 S[4];
    #pragma unroll
    for (int k = 0; k < 4; k++) S[k] = make_float4(0.f, 0.f, 0.f, 0.f);

    for (int c = 0; c < NC; c++) {
        const float e = expf(g_tot[bh*NC + c]);
        const int o = c*1024 + tid;
        #pragma unroll
        for (int k = 0; k < 4; k++) {
            float4 v = st[o + k*256];
            so[o + k*256] = S[k];             // state BEFORE absorbing chunk c
            S[k].x = e * (S[k].x + v.x);
            S[k].y = e * (S[k].y + v.y);
            S[k].z = e * (S[k].z + v.z);
            S[k].w = e * (S[k].w + v.w);
        }
    }
}

// ---------------------------------------------------------------------------
// Pass 3: Y[l][p] += exp(cs[l]) * sum_n C[l][n] * St[n][p]
// 64 threads, 8x8 micro-tile. Ct transposed at load; Ss straight ([n][p]).
// ---------------------------------------------------------------------------
__global__ void __launch_bounds__(64) pass3_kernel(
    const float* __restrict__ C, float* __restrict__ Y)
{
    __shared__ float Ct[64*PAD];   // C transposed: Ct[n][l]
    __shared__ float Ss[64*PAD];   // S [n][p] row-major
    __shared__ float s_ecl[64];

    const int c = blockIdx.x, h = blockIdx.y, b = blockIdx.z;
    const int bhc = (b*NH + h)*NC + c;
    const int tid = threadIdx.x;
    const int tx = tid & 7, ty = tid >> 3;
    const size_t base = ((size_t)((b*4096 + c*BL)*NH + h))*64;
    const float* Sg = g_S + (size_t)bhc*4096;

    s_ecl[tid] = g_ecl[bhc*64 + tid];
    #pragma unroll
    for (int i = 0; i < 8; i++) {
        const int row = i*8 + ty;
        const size_t g = base + (size_t)row*1024 + tx*8;
        float4 c0 = *(const float4*)(C + g);
        float4 c1 = *(const float4*)(C + g + 4);
        const float* cp0 = (const float*)&c0; const float* cp1 = (const float*)&c1;
        #pragma unroll
        for (int q = 0; q < 4; q++) {
            const int e = (q + tx + ty) & 3;
            Ct[(tx*8 + e)*PAD + row]     = cp0[e];
            Ct[(tx*8 + 4 + e)*PAD + row] = cp1[e];
        }
        *(float4*)(Ss + row*PAD + tx*8)     = *(const float4*)(Sg + row*64 + tx*8);
        *(float4*)(Ss + row*PAD + tx*8 + 4) = *(const float4*)(Sg + row*64 + tx*8 + 4);
    }
    __syncthreads();

    const int rb = ty*8, cb = tx*8;
    float acc[8][8] = {};
    #pragma unroll 4
    for (int k = 0; k < 64; k++) {
        float a[8], bb[8];
        *(float4*)(a)      = *(const float4*)(Ct + k*PAD + rb);
        *(float4*)(a + 4)  = *(const float4*)(Ct + k*PAD + rb + 4);
        *(float4*)(bb)     = *(const float4*)(Ss + k*PAD + cb);
        *(float4*)(bb + 4) = *(const float4*)(Ss + k*PAD + cb + 4);
        #pragma unroll
        for (int i = 0; i < 8; i++)
            #pragma unroll
            for (int j = 0; j < 8; j++)
                acc[i][j] += a[i] * bb[j];
    }

    #pragma unroll
    for (int i = 0; i < 8; i++) {
        const float el = s_ecl[rb + i];
        float* yp = Y + base + (size_t)(rb + i)*1024 + cb;
        float4 y0 = *(float4*)(yp);
        float4 y1 = *(float4*)(yp + 4);
        y0.x += el*acc[i][0]; y0.y += el*acc[i][1]; y0.z += el*acc[i][2]; y0.w += el*acc[i][3];
        y1.x += el*acc[i][4]; y1.y += el*acc[i][5]; y1.z += el*acc[i][6]; y1.w += el*acc[i][7];
        *(float4*)(yp)     = y0;
        *(float4*)(yp + 4) = y1;
    }
}

// ---------------------------------------------------------------------------
extern "C" void kernel_launch(void* const* d_in, const int* in_sizes, int n_in,
                              void* d_out, int out_size)
{
    const float* X = (const float*)d_in[0];
    const float* A = (const float*)d_in[1];
    const float* B = (const float*)d_in[2];
    const float* C = (const float*)d_in[3];
    float* Y = (float*)d_out;

    const int smem1 = 3 * 64 * PAD * sizeof(float);   // 52,224 B
    cudaFuncSetAttribute(pass1_kernel,
                         cudaFuncAttributeMaxDynamicSharedMemorySize, smem1);

    dim3 grid(NC, NH, NB);
    pass1_kernel<<<grid, 64, smem1>>>(X, A, B, C, Y);
    pass2_kernel<<<32, 256>>>();
    pass3_kernel<<<grid, 64>>>(C, Y);
}

// round 4
// speedup vs baseline: 1.5520x; 1.5520x over previous
#include <cuda_runtime.h>

// Problem constants: b=2, s=4096, h=16, p=n=64, BLOCK_LEN=64
#define NB  2
#define NH  16
#define NC  64
#define PAD 68   // smem row stride (floats): mult of 4 -> float4-aligned rows

typedef unsigned long long ull;

__device__ __forceinline__ ull ffma2(ull a, ull b, ull c) {
    ull d;
    asm("fma.rn.f32x2 %0, %1, %2, %3;" : "=l"(d) : "l"(a), "l"(b), "l"(c));
    return d;
}
__device__ __forceinline__ ull pack2(float x, float y) {
    ull d; asm("mov.b64 %0, {%1, %2};" : "=l"(d) : "f"(x), "f"(y)); return d;
}
__device__ __forceinline__ float2 unpk(ull v) {
    float2 r; asm("mov.b64 {%0, %1}, %2;" : "=f"(r.x), "=f"(r.y) : "l"(v)); return r;
}

// Scratch (__device__ globals; allocation-free rule)
__device__ float g_states[NB*NH*NC*64*64];  // chunk states [n][p]; scanned in place
__device__ float g_tot[NB*NH*NC];           // per-chunk A totals

// ---------------------------------------------------------------------------
// Pass 1: states only. St[n][p] = sum_l (B[l][n]*w[l]) * X[l][p], w=exp(tot-cs).
// No transposes needed: both operands k(=l)-major as stored.
// ---------------------------------------------------------------------------
__global__ void __launch_bounds__(256) pass1_kernel(
    const float* __restrict__ X, const float* __restrict__ A,
    const float* __restrict__ B)
{
    __shared__ float Xs[64*PAD];
    __shared__ float Bw[64*PAD];
    __shared__ float s_cs[64], s_w[64];

    const int c = blockIdx.x, h = blockIdx.y, b = blockIdx.z;
    const int bhc = (b*NH + h)*NC + c;
    const int tid = threadIdx.x;
    const int tx = tid & 15, ty = tid >> 4;
    const size_t base = ((size_t)((b*4096 + c*64)*NH + h))*64;

    // cumsum of A (2 warps)
    if (tid < 64) {
        float v = A[(size_t)(b*4096 + c*64 + tid)*NH + h];
        float orig = v;
        #pragma unroll
        for (int o = 1; o < 32; o <<= 1) {
            float t = __shfl_up_sync(0xffffffffu, v, o);
            if ((tid & 31) >= o) v += t;
        }
        s_cs[tid] = v;
        (void)orig;
    }
    __syncthreads();
    if (tid >= 32 && tid < 64) s_cs[tid] += s_cs[31];
    __syncthreads();
    if (tid < 64) {
        const float total = s_cs[63];
        s_w[tid] = expf(total - s_cs[tid]);
        if (tid == 63) g_tot[bhc] = total;
    }
    __syncthreads();

    // loads: X straight; B scaled by w[row]
    const int col4 = tx*4;
    #pragma unroll
    for (int i = 0; i < 4; i++) {
        const int row = ty + i*16;
        const size_t g = base + (size_t)row*1024 + col4;
        *(float4*)(Xs + row*PAD + col4) = *(const float4*)(X + g);
        float4 bf = *(const float4*)(B + g);
        const float w = s_w[row];
        bf.x *= w; bf.y *= w; bf.z *= w; bf.w *= w;
        *(float4*)(Bw + row*PAD + col4) = bf;
    }
    __syncthreads();

    // GEMM3 (FFMA2): rows n (rb), cols p (cb)
    const int rb = ty*4, cb = tx*4;
    ull acc[4][2] = {};
    #pragma unroll 4
    for (int k = 0; k < 64; k++) {
        float4 af = *(const float4*)(Bw + k*PAD + rb);
        float4 bf = *(const float4*)(Xs + k*PAD + cb);
        const ull* bp = (const ull*)&bf;
        ull a0 = pack2(af.x, af.x), a1 = pack2(af.y, af.y);
        ull a2 = pack2(af.z, af.z), a3 = pack2(af.w, af.w);
        acc[0][0] = ffma2(a0, bp[0], acc[0][0]); acc[0][1] = ffma2(a0, bp[1], acc[0][1]);
        acc[1][0] = ffma2(a1, bp[0], acc[1][0]); acc[1][1] = ffma2(a1, bp[1], acc[1][1]);
        acc[2][0] = ffma2(a2, bp[0], acc[2][0]); acc[2][1] = ffma2(a2, bp[1], acc[2][1]);
        acc[3][0] = ffma2(a3, bp[0], acc[3][0]); acc[3][1] = ffma2(a3, bp[1], acc[3][1]);
    }
    float* st = g_states + (size_t)bhc*4096;
    #pragma unroll
    for (int i = 0; i < 4; i++) {
        float2 p0 = unpk(acc[i][0]), p1 = unpk(acc[i][1]);
        *(float4*)(st + (rb+i)*64 + cb) = make_float4(p0.x, p0.y, p1.x, p1.y);
    }
}

// ---------------------------------------------------------------------------
// Pass 2: inter-chunk scan, in place. S_out[c] = S_before; S = e_c*(S + v_c).
// 256 CTAs (32 bh x 8 slices), 128 threads, depth-4 prefetch.
// ---------------------------------------------------------------------------
__global__ void __launch_bounds__(128) pass2_kernel()
{
    __shared__ float se[NC];
    const int slice = blockIdx.x, bh = blockIdx.y;
    const int tid = threadIdx.x;

    if (tid < NC) se[tid] = expf(g_tot[bh*NC + tid]);
    __syncthreads();

    float* p = g_states + (size_t)bh*NC*4096 + slice*512 + tid*4;
    float4 v[4];
    #pragma unroll
    for (int j = 0; j < 4; j++) v[j] = *(float4*)(p + (size_t)j*4096);

    float4 S = make_float4(0.f, 0.f, 0.f, 0.f);
    #pragma unroll 4
    for (int c = 0; c < NC; c++) {
        float4 cur = v[c & 3];
        *(float4*)(p + (size_t)c*4096) = S;           // state BEFORE chunk c
        const float e = se[c];
        S.x = e * (S.x + cur.x);
        S.y = e * (S.y + cur.y);
        S.z = e * (S.z + cur.z);
        S.w = e * (S.w + cur.w);
        if (c + 4 < NC) v[c & 3] = *(float4*)(p + (size_t)(c+4)*4096);
    }
}

// ---------------------------------------------------------------------------
// Pass 3: GEMM1 (masked, ecl folded into Cte) + fused GEMM2+GEMM4 -> Y (1 write)
//   Cte[n][l] = C[l][n]*ecl[l];  Bt[n][s] = B[s][n]
//   GEMM1: Gt[s][l] = (l>=s) ? em[s] * sum_n Bt[n][s]*Cte[n][l] : 0
//   Y[l][p] = sum_s Gt[s][l]*X[s][p] + sum_n Cte[n][l]*St[n][p]
// ---------------------------------------------------------------------------
__global__ void __launch_bounds__(256) pass3_kernel(
    const float* __restrict__ X, const float* __restrict__ A,
    const float* __restrict__ B, const float* __restrict__ C,
    float* __restrict__ Y)
{
    extern __shared__ float sm[];
    float* Xs  = sm;              // X[s][p]
    float* Ss  = sm + 64*PAD;     // St[n][p]
    float* Cte = sm + 2*64*PAD;   // C^T * ecl  [n][l]
    float* BtG = sm + 3*64*PAD;   // B^T [n][s] -> then Gt[s][l]
    __shared__ float s_cs[64], s_ecl[64], s_em[64], s_a[64];

    const int c = blockIdx.x, h = blockIdx.y, b = blockIdx.z;
    const int bhc = (b*NH + h)*NC + c;
    const int tid = threadIdx.x;
    const int tx = tid & 15, ty = tid >> 4;
    const size_t base = ((size_t)((b*4096 + c*64)*NH + h))*64;
    const float* Sg = g_states + (size_t)bhc*4096;

    if (tid < 64) s_a[tid] = A[(size_t)(b*4096 + c*64 + tid)*NH + h];

    // straight loads of X and S
    const int col4 = tx*4;
    #pragma unroll
    for (int i = 0; i < 4; i++) {
        const int row = ty + i*16;
        *(float4*)(Xs + row*PAD + col4) =
            *(const float4*)(X + base + (size_t)row*1024 + col4);
        *(float4*)(Ss + row*PAD + col4) = *(const float4*)(Sg + row*64 + col4);
    }
    __syncthreads();

    // cumsum + per-position scalars
    if (tid < 64) {
        float v = s_a[tid];
        #pragma unroll
        for (int o = 1; o < 32; o <<= 1) {
            float t = __shfl_up_sync(0xffffffffu, v, o);
            if ((tid & 31) >= o) v += t;
        }
        s_cs[tid] = v;
    }
    __syncthreads();
    if (tid >= 32 && tid < 64) s_cs[tid] += s_cs[31];
    __syncthreads();
    if (tid < 64) {
        const float csl = s_cs[tid];
        s_ecl[tid] = expf(csl);              // exp(cs[l])
        s_em[tid]  = expf(s_a[tid] - csl);   // exp(A[s]-cs[s])
    }
    __syncthreads();

    // transposed loads: B -> BtG, C*ecl -> Cte (rotated scalar stores)
    #pragma unroll
    for (int i = 0; i < 4; i++) {
        const int row = ty + i*16;
        const size_t g = base + (size_t)row*1024 + col4;
        float4 bf = *(const float4*)(B + g);
        float4 cf = *(const float4*)(C + g);
        const float e = s_ecl[row];
        cf.x *= e; cf.y *= e; cf.z *= e; cf.w *= e;
        const float* bp = (const float*)&bf;
        const float* cp = (const float*)&cf;
        #pragma unroll
        for (int q = 0; q < 4; q++) {
            const int eq = (q + tx + ty) & 3;        // rotation limits conflicts
            BtG[(col4 + eq)*PAD + row] = bp[eq];
            Cte[(col4 + eq)*PAD + row] = cp[eq];
        }
    }
    __syncthreads();

    const int rb = ty*4, cb = tx*4;

    // ---- GEMM1: D[s][l] = sum_n Bt[n][s] * Cte[n][l]  (rows s, cols l) ----
    {
        ull acc[4][2] = {};
        #pragma unroll 4
        for (int k = 0; k < 64; k++) {
            float4 af = *(const float4*)(BtG + k*PAD + rb);
            float4 bf = *(const float4*)(Cte + k*PAD + cb);
            const ull* bp = (const ull*)&bf;
            ull a0 = pack2(af.x, af.x), a1 = pack2(af.y, af.y);
            ull a2 = pack2(af.z, af.z), a3 = pack2(af.w, af.w);
            acc[0][0] = ffma2(a0, bp[0], acc[0][0]); acc[0][1] = ffma2(a0, bp[1], acc[0][1]);
            acc[1][0] = ffma2(a1, bp[0], acc[1][0]); acc[1][1] = ffma2(a1, bp[1], acc[1][1]);
            acc[2][0] = ffma2(a2, bp[0], acc[2][0]); acc[2][1] = ffma2(a2, bp[1], acc[2][1]);
            acc[3][0] = ffma2(a3, bp[0], acc[3][0]); acc[3][1] = ffma2(a3, bp[1], acc[3][1]);
        }
        __syncthreads();   // all GEMM1 reads done -> overwrite BtG with Gt

        #pragma unroll
        for (int i = 0; i < 4; i++) {
            const int s = rb + i;
            const float em = s_em[s];
            float2 p0 = unpk(acc[i][0]), p1 = unpk(acc[i][1]);
            float4 v;
            v.x = (cb + 0 >= s) ? p0.x * em : 0.f;
            v.y = (cb + 1 >= s) ? p0.y * em : 0.f;
            v.z = (cb + 2 >= s) ? p1.x * em : 0.f;
            v.w = (cb + 3 >= s) ? p1.y * em : 0.f;
            *(float4*)(BtG + s*PAD + cb) = v;   // Gt[s][l], k(=s)-major
        }
    }
    __syncthreads();

    // ---- fused GEMM2+GEMM4: Y[l][p] (rows l, cols p) ----
    ull yac[4][2] = {};
    #pragma unroll 2
    for (int k = 0; k < 64; k++) {
        float4 xf = *(const float4*)(Xs  + k*PAD + cb);
        float4 sf = *(const float4*)(Ss  + k*PAD + cb);
        float4 gf = *(const float4*)(BtG + k*PAD + rb);
        float4 cf = *(const float4*)(Cte + k*PAD + rb);
        const ull* xp = (const ull*)&xf;
        const ull* sp = (const ull*)&sf;
        ull g0 = pack2(gf.x, gf.x), g1 = pack2(gf.y, gf.y);
        ull g2 = pack2(gf.z, gf.z), g3 = pack2(gf.w, gf.w);
        ull c0 = pack2(cf.x, cf.x), c1 = pack2(cf.y, cf.y);
        ull c2 = pack2(cf.z, cf.z), c3 = pack2(cf.w, cf.w);
        yac[0][0] = ffma2(g0, xp[0], yac[0][0]); yac[0][1] = ffma2(g0, xp[1], yac[0][1]);
        yac[1][0] = ffma2(g1, xp[0], yac[1][0]); yac[1][1] = ffma2(g1, xp[1], yac[1][1]);
        yac[2][0] = ffma2(g2, xp[0], yac[2][0]); yac[2][1] = ffma2(g2, xp[1], yac[2][1]);
        yac[3][0] = ffma2(g3, xp[0], yac[3][0]); yac[3][1] = ffma2(g3, xp[1], yac[3][1]);
        yac[0][0] = ffma2(c0, sp[0], yac[0][0]); yac[0][1] = ffma2(c0, sp[1], yac[0][1]);
        yac[1][0] = ffma2(c1, sp[0], yac[1][0]); yac[1][1] = ffma2(c1, sp[1], yac[1][1]);
        yac[2][0] = ffma2(c2, sp[0], yac[2][0]); yac[2][1] = ffma2(c2, sp[1], yac[2][1]);
        yac[3][0] = ffma2(c3, sp[0], yac[3][0]); yac[3][1] = ffma2(c3, sp[1], yac[3][1]);
    }

    #pragma unroll
    for (int i = 0; i < 4; i++) {
        float2 p0 = unpk(yac[i][0]), p1 = unpk(yac[i][1]);
        *(float4*)(Y + base + (size_t)(rb+i)*1024 + cb) =
            make_float4(p0.x, p0.y, p1.x, p1.y);
    }
}

// ---------------------------------------------------------------------------
extern "C" void kernel_launch(void* const* d_in, const int* in_sizes, int n_in,
                              void* d_out, int out_size)
{
    const float* X = (const float*)d_in[0];
    const float* A = (const float*)d_in[1];
    const float* B = (const float*)d_in[2];
    const float* C = (const float*)d_in[3];
    float* Y = (float*)d_out;

    const int smem3 = 4 * 64 * PAD * sizeof(float);   // 69,632 B
    cudaFuncSetAttribute(pass3_kernel,
                         cudaFuncAttributeMaxDynamicSharedMemorySize, smem3);

    dim3 grid(NC, NH, NB);
    pass1_kernel<<<grid, 256>>>(X, A, B);
    pass2_kernel<<<dim3(8, NB*NH), 128>>>();
    pass3_kernel<<<grid, 256, smem3>>>(X, A, B, C, Y);
}

// round 5
// speedup vs baseline: 1.6956x; 1.0926x over previous
#include <cuda_runtime.h>

// Problem constants: b=2, s=4096, h=16, p=n=64, BLOCK_LEN=64
#define NB  2
#define NH  16
#define NC  64
#define PAD 68   // smem row stride (floats): mult of 4 -> float4-aligned rows

typedef unsigned long long ull;

__device__ __forceinline__ ull ffma2(ull a, ull b, ull c) {
    ull d;
    asm("fma.rn.f32x2 %0, %1, %2, %3;" : "=l"(d) : "l"(a), "l"(b), "l"(c));
    return d;
}
__device__ __forceinline__ ull pack2(float x, float y) {
    ull d; asm("mov.b64 %0, {%1, %2};" : "=l"(d) : "f"(x), "f"(y)); return d;
}
__device__ __forceinline__ float2 unpk(ull v) {
    float2 r; asm("mov.b64 {%0, %1}, %2;" : "=f"(r.x), "=f"(r.y) : "l"(v)); return r;
}

// Scratch (__device__ globals; allocation-free rule)
__device__ float g_states[NB*NH*NC*64*64];  // chunk states [n][p]; scanned in place
__device__ float g_tot[NB*NH*NC];           // per-chunk A totals

// ---------------------------------------------------------------------------
// Pass 1: states only. St[n][p] = sum_l (B[l][n]*w[l]) * X[l][p], w=exp(tot-cs).
// 128 threads, 8x4 micro-tile (rows n, cols p).
// ---------------------------------------------------------------------------
__global__ void __launch_bounds__(128) pass1_kernel(
    const float* __restrict__ X, const float* __restrict__ A,
    const float* __restrict__ B)
{
    __shared__ float Xs[64*PAD];
    __shared__ float Bw[64*PAD];
    __shared__ float s_cs[64], s_w[64];

    const int c = blockIdx.x, h = blockIdx.y, b = blockIdx.z;
    const int bhc = (b*NH + h)*NC + c;
    const int tid = threadIdx.x;
    const int tx = tid & 15, ty = tid >> 4;
    const size_t base = ((size_t)((b*4096 + c*64)*NH + h))*64;

    // inclusive cumsum of A (threads 0..63)
    if (tid < 64) {
        float v = A[(size_t)(b*4096 + c*64 + tid)*NH + h];
        #pragma unroll
        for (int o = 1; o < 32; o <<= 1) {
            float t = __shfl_up_sync(0xffffffffu, v, o);
            if ((tid & 31) >= o) v += t;
        }
        s_cs[tid] = v;
    }
    __syncthreads();
    if (tid >= 32 && tid < 64) s_cs[tid] += s_cs[31];
    __syncthreads();
    if (tid < 64) {
        const float total = s_cs[63];
        s_w[tid] = expf(total - s_cs[tid]);
        if (tid == 63) g_tot[bhc] = total;
    }
    __syncthreads();

    // loads: X straight; B scaled by w[row]
    const int col4 = tx*4;
    #pragma unroll
    for (int i = 0; i < 8; i++) {
        const int row = i*8 + ty;
        const size_t g = base + (size_t)row*1024 + col4;
        *(float4*)(Xs + row*PAD + col4) = *(const float4*)(X + g);
        float4 bf = *(const float4*)(B + g);
        const float w = s_w[row];
        bf.x *= w; bf.y *= w; bf.z *= w; bf.w *= w;
        *(float4*)(Bw + row*PAD + col4) = bf;
    }
    __syncthreads();

    // GEMM3: rows n (rb, 8 wide), cols p (cb, 4 wide)
    const int rb = ty*8, cb = tx*4;
    ull acc[8][2] = {};
    #pragma unroll 4
    for (int k = 0; k < 64; k++) {
        float af[8];
        *(float4*)(af)     = *(const float4*)(Bw + k*PAD + rb);
        *(float4*)(af + 4) = *(const float4*)(Bw + k*PAD + rb + 4);
        float4 xf = *(const float4*)(Xs + k*PAD + cb);
        const ull* xp = (const ull*)&xf;
        #pragma unroll
        for (int i = 0; i < 8; i++) {
            const ull ad = pack2(af[i], af[i]);
            acc[i][0] = ffma2(ad, xp[0], acc[i][0]);
            acc[i][1] = ffma2(ad, xp[1], acc[i][1]);
        }
    }
    float* st = g_states + (size_t)bhc*4096;
    #pragma unroll
    for (int i = 0; i < 8; i++) {
        float2 p0 = unpk(acc[i][0]), p1 = unpk(acc[i][1]);
        *(float4*)(st + (rb+i)*64 + cb) = make_float4(p0.x, p0.y, p1.x, p1.y);
    }
}

// ---------------------------------------------------------------------------
// Pass 2: inter-chunk scan, in place. S_out[c] = S_before; S = e_c*(S + v_c).
// 256 CTAs (32 bh x 8 slices), 128 threads, depth-8 prefetch.
// ---------------------------------------------------------------------------
__global__ void __launch_bounds__(128) pass2_kernel()
{
    __shared__ float se[NC];
    const int slice = blockIdx.x, bh = blockIdx.y;
    const int tid = threadIdx.x;

    if (tid < NC) se[tid] = expf(g_tot[bh*NC + tid]);
    __syncthreads();

    float* p = g_states + (size_t)bh*NC*4096 + slice*512 + tid*4;
    float4 v[8];
    #pragma unroll
    for (int j = 0; j < 8; j++) v[j] = *(float4*)(p + (size_t)j*4096);

    float4 S = make_float4(0.f, 0.f, 0.f, 0.f);
    #pragma unroll 8
    for (int c = 0; c < NC; c++) {
        float4 cur = v[c & 7];
        *(float4*)(p + (size_t)c*4096) = S;           // state BEFORE chunk c
        const float e = se[c];
        S.x = e * (S.x + cur.x);
        S.y = e * (S.y + cur.y);
        S.z = e * (S.z + cur.z);
        S.w = e * (S.w + cur.w);
        if (c + 8 < NC) v[c & 7] = *(float4*)(p + (size_t)(c+8)*4096);
    }
}

// ---------------------------------------------------------------------------
// Pass 3: GEMM1 (masked, ecl folded into Cte) + fused GEMM2+GEMM4 -> Y (1 write)
//   Cte[n][l] = C[l][n]*ecl[l];  Bt[n][s] = B[s][n]
//   GEMM1: Gt[s][l] = (l>=s) ? em[s] * sum_n Bt[n][s]*Cte[n][l] : 0
//   Y[l][p] = sum_s Gt[s][l]*X[s][p] + sum_n Cte[n][l]*St[n][p]
// 128 threads, 8x4 micro-tiles.
// ---------------------------------------------------------------------------
__global__ void __launch_bounds__(128) pass3_kernel(
    const float* __restrict__ X, const float* __restrict__ A,
    const float* __restrict__ B, const float* __restrict__ C,
    float* __restrict__ Y)
{
    extern __shared__ float sm[];
    float* Xs  = sm;              // X[s][p]
    float* Ss  = sm + 64*PAD;     // St[n][p]
    float* Cte = sm + 2*64*PAD;   // C^T * ecl  [n][l]
    float* BtG = sm + 3*64*PAD;   // B^T [n][s] -> then Gt[s][l]
    __shared__ float s_cs[64], s_ecl[64], s_em[64];

    const int c = blockIdx.x, h = blockIdx.y, b = blockIdx.z;
    const int bhc = (b*NH + h)*NC + c;
    const int tid = threadIdx.x;
    const int tx = tid & 15, ty = tid >> 4;
    const size_t base = ((size_t)((b*4096 + c*64)*NH + h))*64;
    const float* Sg = g_states + (size_t)bhc*4096;

    // cumsum of A (threads 0..63)
    if (tid < 64) {
        float av = A[(size_t)(b*4096 + c*64 + tid)*NH + h];
        float v = av;
        #pragma unroll
        for (int o = 1; o < 32; o <<= 1) {
            float t = __shfl_up_sync(0xffffffffu, v, o);
            if ((tid & 31) >= o) v += t;
        }
        s_cs[tid] = v;
        s_em[tid] = av;   // stash A temporarily
    }

    // straight loads of X and S (independent of cumsum)
    const int col4 = tx*4;
    #pragma unroll
    for (int i = 0; i < 8; i++) {
        const int row = i*8 + ty;
        *(float4*)(Xs + row*PAD + col4) =
            *(const float4*)(X + base + (size_t)row*1024 + col4);
        *(float4*)(Ss + row*PAD + col4) = *(const float4*)(Sg + row*64 + col4);
    }
    __syncthreads();
    if (tid >= 32 && tid < 64) s_cs[tid] += s_cs[31];
    __syncthreads();
    if (tid < 64) {
        const float csl = s_cs[tid];
        s_ecl[tid] = expf(csl);               // exp(cs[l])
        s_em[tid]  = expf(s_em[tid] - csl);   // exp(A[s]-cs[s])
    }
    __syncthreads();

    // transposed loads: B -> BtG, C*ecl -> Cte (rotated scalar stores, <=2-way)
    #pragma unroll
    for (int i = 0; i < 8; i++) {
        const int row = i*8 + ty;
        const size_t g = base + (size_t)row*1024 + col4;
        float4 bf = *(const float4*)(B + g);
        float4 cf = *(const float4*)(C + g);
        const float e = s_ecl[row];
        cf.x *= e; cf.y *= e; cf.z *= e; cf.w *= e;
        const float* bp = (const float*)&bf;
        const float* cp = (const float*)&cf;
        #pragma unroll
        for (int q = 0; q < 4; q++) {
            const int eq = (q + (tx >> 1)) & 3;
            BtG[(col4 + eq)*PAD + row] = bp[eq];
            Cte[(col4 + eq)*PAD + row] = cp[eq];
        }
    }
    __syncthreads();

    const int rb = ty*8, cb = tx*4;

    // ---- GEMM1: Gt[s][l] = sum_n Bt[n][s] * Cte[n][l]  (rows s=rb, cols l=cb) ----
    {
        ull acc[8][2] = {};
        #pragma unroll 4
        for (int k = 0; k < 64; k++) {
            float af[8];
            *(float4*)(af)     = *(const float4*)(BtG + k*PAD + rb);
            *(float4*)(af + 4) = *(const float4*)(BtG + k*PAD + rb + 4);
            float4 bf = *(const float4*)(Cte + k*PAD + cb);
            const ull* bp = (const ull*)&bf;
            #pragma unroll
            for (int i = 0; i < 8; i++) {
                const ull ad = pack2(af[i], af[i]);
                acc[i][0] = ffma2(ad, bp[0], acc[i][0]);
                acc[i][1] = ffma2(ad, bp[1], acc[i][1]);
            }
        }
        __syncthreads();   // all GEMM1 reads done -> overwrite BtG with Gt

        #pragma unroll
        for (int i = 0; i < 8; i++) {
            const int s = rb + i;
            const float em = s_em[s];
            float2 p0 = unpk(acc[i][0]), p1 = unpk(acc[i][1]);
            float4 v;
            v.x = (cb + 0 >= s) ? p0.x * em : 0.f;
            v.y = (cb + 1 >= s) ? p0.y * em : 0.f;
            v.z = (cb + 2 >= s) ? p1.x * em : 0.f;
            v.w = (cb + 3 >= s) ? p1.y * em : 0.f;
            *(float4*)(BtG + s*PAD + cb) = v;   // Gt[s][l], k(=s)-major
        }
    }
    __syncthreads();

    // ---- fused GEMM2+GEMM4: Y[l][p] (rows l=rb 8-wide, cols p=cb 4-wide) ----
    ull yac[8][2] = {};
    #pragma unroll 2
    for (int k = 0; k < 64; k++) {
        float gf[8], cf[8];
        *(float4*)(gf)     = *(const float4*)(BtG + k*PAD + rb);
        *(float4*)(gf + 4) = *(const float4*)(BtG + k*PAD + rb + 4);
        *(float4*)(cf)     = *(const float4*)(Cte + k*PAD + rb);
        *(float4*)(cf + 4) = *(const float4*)(Cte + k*PAD + rb + 4);
        float4 xf = *(const float4*)(Xs + k*PAD + cb);
        float4 sf = *(const float4*)(Ss + k*PAD + cb);
        const ull* xp = (const ull*)&xf;
        const ull* sp = (const ull*)&sf;
        #pragma unroll
        for (int i = 0; i < 8; i++) {
            const ull gd = pack2(gf[i], gf[i]);
            yac[i][0] = ffma2(gd, xp[0], yac[i][0]);
            yac[i][1] = ffma2(gd, xp[1], yac[i][1]);
        }
        #pragma unroll
        for (int i = 0; i < 8; i++) {
            const ull cd = pack2(cf[i], cf[i]);
            yac[i][0] = ffma2(cd, sp[0], yac[i][0]);
            yac[i][1] = ffma2(cd, sp[1], yac[i][1]);
        }
    }

    #pragma unroll
    for (int i = 0; i < 8; i++) {
        float2 p0 = unpk(yac[i][0]), p1 = unpk(yac[i][1]);
        *(float4*)(Y + base + (size_t)(rb+i)*1024 + cb) =
            make_float4(p0.x, p0.y, p1.x, p1.y);
    }
}

// ---------------------------------------------------------------------------
extern "C" void kernel_launch(void* const* d_in, const int* in_sizes, int n_in,
                              void* d_out, int out_size)
{
    const float* X = (const float*)d_in[0];
    const float* A = (const float*)d_in[1];
    const float* B = (const float*)d_in[2];
    const float* C = (const float*)d_in[3];
    float* Y = (float*)d_out;

    const int smem3 = 4 * 64 * PAD * sizeof(float);   // 69,632 B
    cudaFuncSetAttribute(pass3_kernel,
                         cudaFuncAttributeMaxDynamicSharedMemorySize, smem3);

    dim3 grid(NC, NH, NB);
    pass1_kernel<<<grid, 128>>>(X, A, B);
    pass2_kernel<<<dim3(8, NB*NH), 128>>>();
    pass3_kernel<<<grid, 128, smem3>>>(X, A, B, C, Y);
}